// round 16
// baseline (speedup 1.0000x reference)
#include <cuda_runtime.h>
#include <cuda_fp16.h>
#include <math.h>
#include <stdint.h>
#include <string.h>

// ---------------- problem constants ----------------
#define R_RAYS      4096
#define S_SAMPLES   32
#define RS_TOTAL    131072
#define M_SAMPLES   6
#define NUM_LEVELS  10
#define FEAT_DIM    40
#define HASHMASK    2097151u
#define RGB_ELEMS   393216

#define ROWS_CTA    64
#define NCHUNK      (RS_TOTAL / ROWS_CTA)     // 2048 MLP chunks
#define NENC        148                       // encoder CTAs (one per SM in wave 1)
#define NSTRIPE     4
#define ROWS_STRIPE (RS_TOTAL / NSTRIPE)      // 32768
#define RB_PER_STRIPE 128                     // 256-row blocks per stripe
#define NTASK       (NSTRIPE * NUM_LEVELS * RB_PER_STRIPE)   // 5120

__constant__ int c_offsets[NUM_LEVELS] = {
    0, 4920, 40864, 315496, 2412648, 4509800, 6606952, 8704104, 10801256, 12898408
};
__constant__ int c_sizes[NUM_LEVELS] = {
    4920, 35944, 274632, 2097152, 2097152, 2097152, 2097152, 2097152, 2097152, 2097152
};

// fp16 feature scratch + readiness counters
__device__ __half g_feat_h[RS_TOTAL * FEAT_DIM];
__device__ unsigned g_cnt[NCHUNK];

// packed fp16 weight fragments. Layer bases (half2):
//   L1 = 0      (1536)   KT3,  N=64
//   L2 = 1536   (8192)   KT4,  N=256
//   L3 = 9728   (32768)  KT16, N=256  (x only; dir folded into bias)
//   L4 = 42496  (65536)  KT32, N=256  (h2|x only)
#define PK_TOTAL_H2 108032
__device__ __align__(16) __half2 Wpk[PK_TOTAL_H2];

#define SLAB 568   // slab row stride in halves

// ---------------- small helpers ----------------
__device__ __forceinline__ unsigned long long pack_h2x2(__half2 lo, __half2 hi) {
    unsigned ulo, uhi;
    memcpy(&ulo, &lo, 4);
    memcpy(&uhi, &hi, 4);
    return ((unsigned long long)uhi << 32) | ulo;
}

__device__ __forceinline__ unsigned smem_u32(const void* p) {
    unsigned a;
    asm("{ .reg .u64 t; cvta.to.shared.u64 t, %1; cvt.u32.u64 %0, t; }" : "=r"(a) : "l"(p));
    return a;
}

__device__ __forceinline__ void ldsm_x4(unsigned &a0, unsigned &a1,
                                        unsigned &a2, unsigned &a3, unsigned addr) {
    asm volatile("ldmatrix.sync.aligned.m8n8.x4.shared.b16 {%0,%1,%2,%3}, [%4];"
                 : "=r"(a0), "=r"(a1), "=r"(a2), "=r"(a3) : "r"(addr));
}

__device__ __forceinline__ void mma16816(float c[4],
    unsigned a0, unsigned a1, unsigned a2, unsigned a3,
    unsigned b0, unsigned b1)
{
    asm volatile(
        "mma.sync.aligned.m16n8k16.row.col.f32.f16.f16.f32 "
        "{%0,%1,%2,%3}, {%4,%5,%6,%7}, {%8,%9}, {%0,%1,%2,%3};"
        : "+f"(c[0]), "+f"(c[1]), "+f"(c[2]), "+f"(c[3])
        : "r"(a0), "r"(a1), "r"(a2), "r"(a3), "r"(b0), "r"(b1));
}

// ---------------- kernel 0: weight prep + counter reset ----------------
__global__ __launch_bounds__(256) void prep_kernel(
    const float* __restrict__ dw1, const float* __restrict__ dw2,
    const float* __restrict__ vw0, const float* __restrict__ vw1)
{
    int idx = blockIdx.x * 256 + threadIdx.x;
    if (idx < NCHUNK) g_cnt[idx] = 0;
    if (idx >= PK_TOTAL_H2) return;

    int local, NP, layer;
    if (idx < 1536)        { layer = 1; local = idx;         NP = 4;  }
    else if (idx < 9728)   { layer = 2; local = idx - 1536;  NP = 16; }
    else if (idx < 42496)  { layer = 3; local = idx - 9728;  NP = 16; }
    else                   { layer = 4; local = idx - 42496; NP = 16; }

    const int j    = local & 3;
    const int lane = (local >> 2) & 31;
    const int rem  = local >> 7;
    const int np   = rem % NP;
    const int kt   = rem / NP;

    const int nt  = np * 2 + (j >> 1);
    const int reg = j & 1;
    const int n   = nt * 8 + (lane >> 2);
    const int k   = kt * 16 + reg * 8 + (lane & 3) * 2;

    float v0 = 0.f, v1 = 0.f;
    if (layer == 1) {
        if (k     < 40) v0 = dw1[k * 64 + n];
        if (k + 1 < 40) v1 = dw1[(k + 1) * 64 + n];
    } else if (layer == 2) {
        v0 = dw2[k * 256 + n];
        v1 = dw2[(k + 1) * 256 + n];
    } else if (layer == 3) {
        v0 = vw0[k * 256 + n];
        v1 = vw0[(k + 1) * 256 + n];
    } else {
        v0 = vw1[k * 256 + n];
        v1 = vw1[(k + 1) * 256 + n];
    }
    Wpk[idx] = __floats2half2_rn(v0, v1);
}

// ---------------- L1 fragment-GEMM (R9 mapping): warp = 2 m-tiles x 2 n-tiles ----------------
template<int KT, int NTW, int NP>
__device__ __forceinline__ void run_layer2(
    const __half* slab, int acol0, int mp, int gr, int gc,
    const __half2* __restrict__ wpk, int nq, int lane, float C[2][NTW][4])
{
    const __half* arow0 = slab + (mp * 32 + gr) * SLAB + acol0 + gc * 2;
    const uint4* wbase = (const uint4*)wpk + (size_t)(nq * (NTW / 2)) * 32 + lane;
    #pragma unroll 1
    for (int kt = 0; kt < KT; kt++) {
        const __half* ap0 = arow0 + kt * 16;
        const __half* ap1 = ap0 + 16 * SLAB;
        unsigned a0 = *(const unsigned*)(ap0);
        unsigned a2 = *(const unsigned*)(ap0 + 8);
        unsigned a1 = *(const unsigned*)(ap0 + 8 * SLAB);
        unsigned a3 = *(const unsigned*)(ap0 + 8 * SLAB + 8);
        unsigned a4 = *(const unsigned*)(ap1);
        unsigned a6 = *(const unsigned*)(ap1 + 8);
        unsigned a5 = *(const unsigned*)(ap1 + 8 * SLAB);
        unsigned a7 = *(const unsigned*)(ap1 + 8 * SLAB + 8);
        const uint4* wp = wbase + (size_t)kt * NP * 32;
        #pragma unroll
        for (int p = 0; p < NTW / 2; p++) {
            uint4 b = __ldg(wp + p * 32);
            mma16816(C[0][2 * p],     a0, a1, a2, a3, b.x, b.y);
            mma16816(C[0][2 * p + 1], a0, a1, a2, a3, b.z, b.w);
            mma16816(C[1][2 * p],     a4, a5, a6, a7, b.x, b.y);
            mma16816(C[1][2 * p + 1], a4, a5, a6, a7, b.z, b.w);
        }
    }
}

// ---------------- L2-L4 fragment-GEMM: warp = 4 m-tiles x 4 n-tiles ----------
// A via ldmatrix.x4; B double-buffered LDG.128.
template<int KT>
__device__ __forceinline__ void run_layer4(
    const __half* slab, int acol0, int lane,
    const __half2* __restrict__ wpk, int nq, float C[4][4][4])
{
    const int arow = ((lane >> 3) & 1) * 8 + (lane & 7);
    const unsigned abase = smem_u32(slab)
        + (unsigned)((arow * SLAB + acol0 + (lane >> 4) * 8) * 2);

    const uint4* wbase = (const uint4*)wpk + (size_t)(nq * 2) * 32 + lane;
    uint4 b0 = __ldg(wbase);
    uint4 b1 = __ldg(wbase + 32);
    #pragma unroll 1
    for (int kt = 0; kt < KT; kt++) {
        const uint4 cur0 = b0, cur1 = b1;
        if (kt + 1 < KT) {
            const uint4* wp = wbase + (size_t)(kt + 1) * 16 * 32;
            b0 = __ldg(wp);
            b1 = __ldg(wp + 32);
        }
        #pragma unroll
        for (int m = 0; m < 4; m++) {
            unsigned a0, a1, a2, a3;
            ldsm_x4(a0, a1, a2, a3,
                    abase + (unsigned)(m * 16 * SLAB * 2 + kt * 32));
            mma16816(C[m][0], a0, a1, a2, a3, cur0.x, cur0.y);
            mma16816(C[m][1], a0, a1, a2, a3, cur0.z, cur0.w);
            mma16816(C[m][2], a0, a1, a2, a3, cur1.x, cur1.y);
            mma16816(C[m][3], a0, a1, a2, a3, cur1.z, cur1.w);
        }
    }
}

// ---------------- fused kernel: 148 encoder CTAs + 2048 MLP CTAs ----------------
// smem (MLP branch): slab 64x568 halves | dirsm 64f | d3s 512f | d4s 512f | rwsm 768f | parth 1536f
#define SM_DIR   72704
#define SM_D3    72960
#define SM_D4    75008
#define SM_RW    77056
#define SM_PARTH 80128
#define SM_TOTAL 86272

__global__ __launch_bounds__(256, 2) void fused2_kernel(
    const float* __restrict__ means,
    const float* __restrict__ stds,
    const float4* __restrict__ table,
    const float* __restrict__ vd,
    const float* __restrict__ db1, const float* __restrict__ db2,
    const float* __restrict__ vb0, const float* __restrict__ vb1,
    const float* __restrict__ vw0, const float* __restrict__ vw1,
    const float* __restrict__ rw,  const float* __restrict__ rbias,
    float* __restrict__ out)
{
    const int t = threadIdx.x;

    // ================= ENCODER CTAs =================
    if (blockIdx.x < NENC) {
        #pragma unroll 1
        for (int task = blockIdx.x; task < NTASK; task += NENC) {
            const int s     = task / (NUM_LEVELS * RB_PER_STRIPE);
            const int rem   = task % (NUM_LEVELS * RB_PER_STRIPE);
            const int level = rem / RB_PER_STRIPE;
            const int rb    = rem % RB_PER_STRIPE;
            const int rowbase = s * ROWS_STRIPE + rb * 256;
            const int rs = rowbase + t;

            const float scale = (float)(16 << level);
            const unsigned res = (unsigned)((16 << level) + 1);
            const bool dense = (level < 3);
            const int off = c_offsets[level];
            const unsigned size_m1 = (unsigned)(c_sizes[level] - 1);

            float acc0 = 0.f, acc1 = 0.f, acc2 = 0.f, acc3 = 0.f;

            // unroll 1: ~70 regs -> NO spill under the 128-reg cap (the R11/R12 bug).
            #pragma unroll 1
            for (int m = 0; m < M_SAMPLES; m++) {
                const int pidx = rs * M_SAMPLES + m;
                const float mx = means[pidx * 3 + 0];
                const float my = means[pidx * 3 + 1];
                const float mz = means[pidx * 3 + 2];
                const float sd = stds[pidx];
                const float wl = erff(1.0f / (2.8284271247461903f * sd * scale));

                float px = (mx + 1.0f) * 0.5f * scale + 0.5f;
                float py = (my + 1.0f) * 0.5f * scale + 0.5f;
                float pz = (mz + 1.0f) * 0.5f * scale + 0.5f;
                float f0x = floorf(px), f0y = floorf(py), f0z = floorf(pz);
                float fx = px - f0x, fy = py - f0y, fz = pz - f0z;
                unsigned ux = (unsigned)f0x, uy = (unsigned)f0y, uz = (unsigned)f0z;

                #pragma unroll
                for (int c = 0; c < 8; c++) {
                    const unsigned bx = c & 1u, by = (c >> 1) & 1u, bz = (c >> 2) & 1u;
                    const unsigned cx = ux + bx, cy = uy + by, cz = uz + bz;
                    unsigned idx;
                    if (dense) { idx = (cx * res + cy) * res + cz; idx = min(idx, size_m1); }
                    else { idx = (cx * 1u) ^ (cy * 2654435761u) ^ (cz * 805459861u); idx &= HASHMASK; }
                    const float wx = bx ? fx : (1.0f - fx);
                    const float wy = by ? fy : (1.0f - fy);
                    const float wz = bz ? fz : (1.0f - fz);
                    const float w = wx * wy * wz * wl;
                    const float4 tt = __ldg(table + off + (int)idx);
                    acc0 += w * tt.x; acc1 += w * tt.y; acc2 += w * tt.z; acc3 += w * tt.w;
                }
            }
            const float inv = 1.0f / 6.0f;
            const __half2 lo = __floats2half2_rn(acc0 * inv, acc1 * inv);
            const __half2 hi = __floats2half2_rn(acc2 * inv, acc3 * inv);
            *(unsigned long long*)&g_feat_h[rs * FEAT_DIM + level * 4] = pack_h2x2(lo, hi);

            __syncthreads();
            if (t < 4) {
                __threadfence();
                atomicAdd(&g_cnt[(rowbase >> 6) + t], 1u);
            }
        }
        return;
    }

    // ================= MLP CTAs =================
    extern __shared__ char dyn[];
    __half* slab = (__half*)dyn;
    float* dirsm = (float*)(dyn + SM_DIR);
    float* d3s   = (float*)(dyn + SM_D3);
    float* d4s   = (float*)(dyn + SM_D4);
    float* rwsm  = (float*)(dyn + SM_RW);
    float* parth = (float*)(dyn + SM_PARTH);

    const int w = t >> 5, lane = t & 31;
    const int gr = lane >> 2, gc = lane & 3;
    const int cta = blockIdx.x - NENC;
    const int rs0 = cta * ROWS_CTA;

    // independent prep first (weights, dir encode, dir-fold), then spin.
    for (int i = t; i < 768; i += 256) rwsm[i] = rw[i];

    if (t < 64) {
        int rayi = t >> 5, c = t & 31;
        int rg = cta * 2 + rayi;
        float v = 0.f;
        if (c < 3) v = vd[rg * 3 + c];
        else if (c < 15) { int j = c - 3;  v = sinf(vd[rg * 3 + (j % 3)] * (float)(1 << (j / 3))); }
        else if (c < 27) { int j = c - 15; v = cosf(vd[rg * 3 + (j % 3)] * (float)(1 << (j / 3))); }
        dirsm[t] = v;
        *(uint4*)&slab[t * SLAB + 40] = make_uint4(0, 0, 0, 0);
    }
    __syncthreads();

    // dir contribution folded to per-(ray,channel) scalars (fp32)
    {
        const int ry = t >> 7;
        const int ch = (t & 127) * 2;
        const float* dv = &dirsm[ry * 32];
        float a3 = 0.f, b3 = 0.f, a4 = 0.f, b4 = 0.f;
        #pragma unroll
        for (int j = 0; j < 27; j++) {
            const float d = dv[j];
            const float2 w3 = *(const float2*)&vw0[(256 + j) * 256 + ch];
            const float2 w4 = *(const float2*)&vw1[(512 + j) * 256 + ch];
            a3 += d * w3.x; b3 += d * w3.y;
            a4 += d * w4.x; b4 += d * w4.y;
        }
        *(float2*)&d3s[ry * 256 + ch] = make_float2(a3, b3);
        *(float2*)&d4s[ry * 256 + ch] = make_float2(a4, b4);
    }

    // ---- wait for this chunk's features (all 10 levels) ----
    if (t == 0) {
        unsigned v;
        do {
            asm volatile("ld.acquire.gpu.b32 %0, [%1];"
                         : "=r"(v) : "l"(&g_cnt[cta]) : "memory");
            if (v < NUM_LEVELS) __nanosleep(128);
        } while (v < NUM_LEVELS);
    }
    __syncthreads();

    // feat (fp16) -> slab cols 0..39
    #pragma unroll
    for (int i = t; i < ROWS_CTA * 20; i += 256) {
        int r = i / 20, c = i % 20;
        *(unsigned*)&slab[r * SLAB + c * 2] =
            *(const unsigned*)&g_feat_h[(rs0 + r) * FEAT_DIM + c * 2];
    }
    __syncthreads();

    // ---- L1: feat(cols 0..47) @ W1 -> h1 (relu) -> cols 64..127 ----
    {
        const int mp = w & 1, nq = w >> 1;
        float C[2][2][4] = {};
        run_layer2<3, 2, 4>(slab, 0, mp, gr, gc, Wpk, nq, lane, C);
        #pragma unroll
        for (int mm = 0; mm < 2; mm++) {
            const int r0 = mp * 32 + mm * 16 + gr;
            #pragma unroll
            for (int nt = 0; nt < 2; nt++) {
                int n = nq * 16 + nt * 8 + 2 * gc;
                float2 b = *(const float2*)&db1[n];
                __half2 lo = __floats2half2_rn(fmaxf(C[mm][nt][0] + b.x, 0.f), fmaxf(C[mm][nt][1] + b.y, 0.f));
                __half2 hi = __floats2half2_rn(fmaxf(C[mm][nt][2] + b.x, 0.f), fmaxf(C[mm][nt][3] + b.y, 0.f));
                *(__half2*)&slab[r0 * SLAB + 64 + n]       = lo;
                *(__half2*)&slab[(r0 + 8) * SLAB + 64 + n] = hi;
            }
        }
    }
    __syncthreads();

    // ---- L2: h1(cols 64..127) @ W2 -> x (cols 256..511); density ----
    {
        float C[4][4][4] = {};
        run_layer4<4>(slab, 64, lane, Wpk + 1536, w, C);
        #pragma unroll
        for (int m = 0; m < 4; m++) {
            const int r0 = m * 16 + gr;
            if (w == 0 && gc == 0) {
                float xa = C[m][0][0] + __ldg(&db2[0]) - 1.0f;
                float xb = C[m][0][2] + __ldg(&db2[0]) - 1.0f;
                out[RGB_ELEMS + rs0 + r0]     = fmaxf(xa, 0.f) + log1pf(expf(-fabsf(xa)));
                out[RGB_ELEMS + rs0 + r0 + 8] = fmaxf(xb, 0.f) + log1pf(expf(-fabsf(xb)));
            }
            #pragma unroll
            for (int nt = 0; nt < 4; nt++) {
                int n = w * 32 + nt * 8 + 2 * gc;
                float2 b = *(const float2*)&db2[n];
                __half2 lo = __floats2half2_rn(C[m][nt][0] + b.x, C[m][nt][1] + b.y);
                __half2 hi = __floats2half2_rn(C[m][nt][2] + b.x, C[m][nt][3] + b.y);
                *(__half2*)&slab[r0 * SLAB + 256 + n]       = lo;
                *(__half2*)&slab[(r0 + 8) * SLAB + 256 + n] = hi;
            }
        }
    }
    __syncthreads();

    // ---- L3: x(cols 256..511) @ W3 + dirfold -> h2 (relu) -> cols 0..255 ----
    {
        float C[4][4][4] = {};
        run_layer4<16>(slab, 256, lane, Wpk + 9728, w, C);
        #pragma unroll
        for (int m = 0; m < 4; m++) {
            const int r0 = m * 16 + gr;
            const int ry = m >> 1;
            #pragma unroll
            for (int nt = 0; nt < 4; nt++) {
                int n = w * 32 + nt * 8 + 2 * gc;
                float2 b = *(const float2*)&vb0[n];
                float2 d = *(const float2*)&d3s[ry * 256 + n];
                float b0 = b.x + d.x, b1 = b.y + d.y;
                __half2 lo = __floats2half2_rn(fmaxf(C[m][nt][0] + b0, 0.f), fmaxf(C[m][nt][1] + b1, 0.f));
                __half2 hi = __floats2half2_rn(fmaxf(C[m][nt][2] + b0, 0.f), fmaxf(C[m][nt][3] + b1, 0.f));
                *(__half2*)&slab[r0 * SLAB + n]       = lo;
                *(__half2*)&slab[(r0 + 8) * SLAB + n] = hi;
            }
        }
    }
    __syncthreads();

    // ---- L4: [h2|x](cols 0..511) @ W4 + dirfold -> h3 (regs) -> rgb head ----
    {
        float C[4][4][4] = {};
        run_layer4<32>(slab, 0, lane, Wpk + 42496, w, C);

        #pragma unroll
        for (int m = 0; m < 4; m++) {
            const int r0 = m * 16 + gr;
            const int ry = m >> 1;
            float pl[3] = {0.f, 0.f, 0.f}, ph[3] = {0.f, 0.f, 0.f};
            #pragma unroll
            for (int nt = 0; nt < 4; nt++) {
                int n = w * 32 + nt * 8 + 2 * gc;
                float2 b = *(const float2*)&vb1[n];
                float2 d = *(const float2*)&d4s[ry * 256 + n];
                float b0 = b.x + d.x, b1 = b.y + d.y;
                float h0 = fmaxf(C[m][nt][0] + b0, 0.f);
                float h1 = fmaxf(C[m][nt][1] + b1, 0.f);
                float h2 = fmaxf(C[m][nt][2] + b0, 0.f);
                float h3 = fmaxf(C[m][nt][3] + b1, 0.f);
                #pragma unroll
                for (int j = 0; j < 3; j++) {
                    pl[j] += h0 * rwsm[n * 3 + j] + h1 * rwsm[(n + 1) * 3 + j];
                    ph[j] += h2 * rwsm[n * 3 + j] + h3 * rwsm[(n + 1) * 3 + j];
                }
            }
            #pragma unroll
            for (int j = 0; j < 3; j++) {
                pl[j] += __shfl_xor_sync(0xffffffffu, pl[j], 1);
                pl[j] += __shfl_xor_sync(0xffffffffu, pl[j], 2);
                ph[j] += __shfl_xor_sync(0xffffffffu, ph[j], 1);
                ph[j] += __shfl_xor_sync(0xffffffffu, ph[j], 2);
            }
            if (gc == 0) {
                #pragma unroll
                for (int j = 0; j < 3; j++) {
                    parth[r0 * 24 + w * 3 + j]       = pl[j];
                    parth[(r0 + 8) * 24 + w * 3 + j] = ph[j];
                }
            }
        }
    }
    __syncthreads();

    if (t < ROWS_CTA) {
        #pragma unroll
        for (int j = 0; j < 3; j++) {
            float s = __ldg(&rbias[j]);
            #pragma unroll
            for (int q = 0; q < 8; q++) s += parth[t * 24 + q * 3 + j];
            float sig = 1.0f / (1.0f + expf(-s));
            out[(rs0 + t) * 3 + j] = sig * 1.002f - 0.001f;
        }
    }
}

// ---------------- launch ----------------
extern "C" void kernel_launch(void* const* d_in, const int* in_sizes, int n_in,
                              void* d_out, int out_size)
{
    const float* means = (const float*)d_in[0];
    const float* stds  = (const float*)d_in[1];
    const float* vd    = (const float*)d_in[2];
    const float* table = (const float*)d_in[3];
    const float* dw1   = (const float*)d_in[4];
    const float* db1   = (const float*)d_in[5];
    const float* dw2   = (const float*)d_in[6];
    const float* db2   = (const float*)d_in[7];
    const float* vw0   = (const float*)d_in[8];
    const float* vb0   = (const float*)d_in[9];
    const float* vw1   = (const float*)d_in[10];
    const float* vb1   = (const float*)d_in[11];
    const float* rw    = (const float*)d_in[12];
    const float* rb    = (const float*)d_in[13];
    float* out = (float*)d_out;

    cudaFuncSetAttribute(fused2_kernel, cudaFuncAttributeMaxDynamicSharedMemorySize, SM_TOTAL);

    prep_kernel<<<(PK_TOTAL_H2 + 255) / 256, 256>>>(dw1, dw2, vw0, vw1);

    fused2_kernel<<<NENC + NCHUNK, 256, SM_TOTAL>>>(
        means, stds, (const float4*)table, vd,
        db1, db2, vb0, vb1, vw0, vw1, rw, rb, out);
}

// round 17
// speedup vs baseline: 2.4035x; 2.4035x over previous
#include <cuda_runtime.h>
#include <cuda_fp16.h>
#include <math.h>
#include <stdint.h>
#include <string.h>

// ---------------- problem constants ----------------
#define R_RAYS      4096
#define S_SAMPLES   32
#define RS_TOTAL    131072
#define M_SAMPLES   6
#define NUM_LEVELS  10
#define FEAT_DIM    40
#define HASHMASK    2097151u
#define RGB_ELEMS   393216

#define ROWS_CTA    64
#define NCTA        (RS_TOTAL / ROWS_CTA)     // 2048

// encode: 1D grid, 128 threads; tasks = (level, rowblock)
#define ENC_BLOCKS  (NUM_LEVELS * (RS_TOTAL / 128))   // 10240
// prep appended as trailing blocks (128 threads each)
#define PK_TOTAL_H2 108032
#define PREP_BLOCKS ((PK_TOTAL_H2 + 127) / 128)       // 844

__constant__ int c_offsets[NUM_LEVELS] = {
    0, 4920, 40864, 315496, 2412648, 4509800, 6606952, 8704104, 10801256, 12898408
};
__constant__ int c_sizes[NUM_LEVELS] = {
    4920, 35944, 274632, 2097152, 2097152, 2097152, 2097152, 2097152, 2097152, 2097152
};

// fp16 feature scratch: [rs][40]
__device__ __half g_feat_h[RS_TOTAL * FEAT_DIM];

// packed fp16 weight fragments. Layer bases (half2):
//   L1 = 0      (1536)   KT3,  N=64
//   L2 = 1536   (8192)   KT4,  N=256
//   L3 = 9728   (32768)  KT16, N=256  (x only; dir folded into bias)
//   L4 = 42496  (65536)  KT32, N=256  (h2|x only)
__device__ __align__(16) __half2 Wpk[PK_TOTAL_H2];

#define SLAB 568   // slab row stride in halves

// ---------------- small helpers ----------------
__device__ __forceinline__ unsigned long long pack_h2x2(__half2 lo, __half2 hi) {
    unsigned ulo, uhi;
    memcpy(&ulo, &lo, 4);
    memcpy(&uhi, &hi, 4);
    return ((unsigned long long)uhi << 32) | ulo;
}

__device__ __forceinline__ unsigned smem_u32(const void* p) {
    unsigned a;
    asm("{ .reg .u64 t; cvta.to.shared.u64 t, %1; cvt.u32.u64 %0, t; }" : "=r"(a) : "l"(p));
    return a;
}

__device__ __forceinline__ void ldsm_x4(unsigned &a0, unsigned &a1,
                                        unsigned &a2, unsigned &a3, unsigned addr) {
    asm volatile("ldmatrix.sync.aligned.m8n8.x4.shared.b16 {%0,%1,%2,%3}, [%4];"
                 : "=r"(a0), "=r"(a1), "=r"(a2), "=r"(a3) : "r"(addr));
}

__device__ __forceinline__ void mma16816(float c[4],
    unsigned a0, unsigned a1, unsigned a2, unsigned a3,
    unsigned b0, unsigned b1)
{
    asm volatile(
        "mma.sync.aligned.m16n8k16.row.col.f32.f16.f16.f32 "
        "{%0,%1,%2,%3}, {%4,%5,%6,%7}, {%8,%9}, {%0,%1,%2,%3};"
        : "+f"(c[0]), "+f"(c[1]), "+f"(c[2]), "+f"(c[3])
        : "r"(a0), "r"(a1), "r"(a2), "r"(a3), "r"(b0), "r"(b1));
}

// ---------------- prep work (device function, runs in trailing blocks) ----------------
__device__ __forceinline__ void prep_work(int idx,
    const float* __restrict__ dw1, const float* __restrict__ dw2,
    const float* __restrict__ vw0, const float* __restrict__ vw1)
{
    if (idx >= PK_TOTAL_H2) return;

    int local, NP, layer;
    if (idx < 1536)        { layer = 1; local = idx;         NP = 4;  }
    else if (idx < 9728)   { layer = 2; local = idx - 1536;  NP = 16; }
    else if (idx < 42496)  { layer = 3; local = idx - 9728;  NP = 16; }
    else                   { layer = 4; local = idx - 42496; NP = 16; }

    const int j    = local & 3;
    const int lane = (local >> 2) & 31;
    const int rem  = local >> 7;
    const int np   = rem % NP;
    const int kt   = rem / NP;

    const int nt  = np * 2 + (j >> 1);
    const int reg = j & 1;
    const int n   = nt * 8 + (lane >> 2);
    const int k   = kt * 16 + reg * 8 + (lane & 3) * 2;

    float v0 = 0.f, v1 = 0.f;
    if (layer == 1) {
        if (k     < 40) v0 = dw1[k * 64 + n];
        if (k + 1 < 40) v1 = dw1[(k + 1) * 64 + n];
    } else if (layer == 2) {
        v0 = dw2[k * 256 + n];
        v1 = dw2[(k + 1) * 256 + n];
    } else if (layer == 3) {
        v0 = vw0[k * 256 + n];
        v1 = vw0[(k + 1) * 256 + n];
    } else {
        v0 = vw1[k * 256 + n];
        v1 = vw1[(k + 1) * 256 + n];
    }
    Wpk[idx] = __floats2half2_rn(v0, v1);
}

// ---------------- kernel 1: hash-grid encode (R7-validated) + prep tail ----------------
__global__ __launch_bounds__(128) void grid_encode_kernel(
    const float* __restrict__ means,
    const float* __restrict__ stds,
    const float4* __restrict__ table,
    const float* __restrict__ dw1, const float* __restrict__ dw2,
    const float* __restrict__ vw0, const float* __restrict__ vw1)
{
    if (blockIdx.x >= ENC_BLOCKS) {
        prep_work((blockIdx.x - ENC_BLOCKS) * 128 + threadIdx.x, dw1, dw2, vw0, vw1);
        return;
    }

    const int level = blockIdx.x / (RS_TOTAL / 128);
    const int rs = (blockIdx.x % (RS_TOTAL / 128)) * 128 + threadIdx.x;

    const float scale = (float)(16 << level);
    const unsigned res = (unsigned)((16 << level) + 1);
    const bool dense = (level < 3);
    const int off = c_offsets[level];
    const unsigned size_m1 = (unsigned)(c_sizes[level] - 1);

    float acc0 = 0.f, acc1 = 0.f, acc2 = 0.f, acc3 = 0.f;

    #pragma unroll
    for (int m = 0; m < M_SAMPLES; m++) {
        const int pidx = rs * M_SAMPLES + m;
        const float mx = means[pidx * 3 + 0];
        const float my = means[pidx * 3 + 1];
        const float mz = means[pidx * 3 + 2];
        const float sd = stds[pidx];
        const float wl = erff(1.0f / (2.8284271247461903f * sd * scale));

        float px = (mx + 1.0f) * 0.5f * scale + 0.5f;
        float py = (my + 1.0f) * 0.5f * scale + 0.5f;
        float pz = (mz + 1.0f) * 0.5f * scale + 0.5f;
        float f0x = floorf(px), f0y = floorf(py), f0z = floorf(pz);
        float fx = px - f0x, fy = py - f0y, fz = pz - f0z;
        unsigned ux = (unsigned)f0x, uy = (unsigned)f0y, uz = (unsigned)f0z;

        #pragma unroll
        for (int c = 0; c < 8; c++) {
            const unsigned bx = c & 1u, by = (c >> 1) & 1u, bz = (c >> 2) & 1u;
            const unsigned cx = ux + bx, cy = uy + by, cz = uz + bz;
            unsigned idx;
            if (dense) { idx = (cx * res + cy) * res + cz; idx = min(idx, size_m1); }
            else { idx = (cx * 1u) ^ (cy * 2654435761u) ^ (cz * 805459861u); idx &= HASHMASK; }
            const float wx = bx ? fx : (1.0f - fx);
            const float wy = by ? fy : (1.0f - fy);
            const float wz = bz ? fz : (1.0f - fz);
            const float w = wx * wy * wz * wl;
            const float4 tt = __ldg(table + off + (int)idx);
            acc0 += w * tt.x; acc1 += w * tt.y; acc2 += w * tt.z; acc3 += w * tt.w;
        }
    }
    const float inv = 1.0f / 6.0f;
    const __half2 lo = __floats2half2_rn(acc0 * inv, acc1 * inv);
    const __half2 hi = __floats2half2_rn(acc2 * inv, acc3 * inv);
    *(unsigned long long*)&g_feat_h[rs * FEAT_DIM + level * 4] = pack_h2x2(lo, hi);
}

// ---------------- L1 fragment-GEMM (R9 mapping): warp = 2 m-tiles x 2 n-tiles ----------------
template<int KT, int NTW, int NP>
__device__ __forceinline__ void run_layer2(
    const __half* slab, int acol0, int mp, int gr, int gc,
    const __half2* __restrict__ wpk, int nq, int lane, float C[2][NTW][4])
{
    const __half* arow0 = slab + (mp * 32 + gr) * SLAB + acol0 + gc * 2;
    const uint4* wbase = (const uint4*)wpk + (size_t)(nq * (NTW / 2)) * 32 + lane;
    #pragma unroll 1
    for (int kt = 0; kt < KT; kt++) {
        const __half* ap0 = arow0 + kt * 16;
        const __half* ap1 = ap0 + 16 * SLAB;
        unsigned a0 = *(const unsigned*)(ap0);
        unsigned a2 = *(const unsigned*)(ap0 + 8);
        unsigned a1 = *(const unsigned*)(ap0 + 8 * SLAB);
        unsigned a3 = *(const unsigned*)(ap0 + 8 * SLAB + 8);
        unsigned a4 = *(const unsigned*)(ap1);
        unsigned a6 = *(const unsigned*)(ap1 + 8);
        unsigned a5 = *(const unsigned*)(ap1 + 8 * SLAB);
        unsigned a7 = *(const unsigned*)(ap1 + 8 * SLAB + 8);
        const uint4* wp = wbase + (size_t)kt * NP * 32;
        #pragma unroll
        for (int p = 0; p < NTW / 2; p++) {
            uint4 b = __ldg(wp + p * 32);
            mma16816(C[0][2 * p],     a0, a1, a2, a3, b.x, b.y);
            mma16816(C[0][2 * p + 1], a0, a1, a2, a3, b.z, b.w);
            mma16816(C[1][2 * p],     a4, a5, a6, a7, b.x, b.y);
            mma16816(C[1][2 * p + 1], a4, a5, a6, a7, b.z, b.w);
        }
    }
}

// ---------------- L2-L4 fragment-GEMM: warp = 4 m-tiles x 4 n-tiles ----------
// A loaded via ldmatrix.x4 (1 LDSM per m-tile per kt); B double-buffered LDG.128.
template<int KT>
__device__ __forceinline__ void run_layer4(
    const __half* slab, int acol0, int lane,
    const __half2* __restrict__ wpk, int nq, float C[4][4][4])
{
    // per-lane ldmatrix address: row = ((lane>>3)&1)*8 + (lane&7), colhalf = lane>>4
    const int arow = ((lane >> 3) & 1) * 8 + (lane & 7);
    const unsigned abase = smem_u32(slab)
        + (unsigned)((arow * SLAB + acol0 + (lane >> 4) * 8) * 2);

    const uint4* wbase = (const uint4*)wpk + (size_t)(nq * 2) * 32 + lane;
    uint4 b0 = __ldg(wbase);
    uint4 b1 = __ldg(wbase + 32);
    #pragma unroll 1
    for (int kt = 0; kt < KT; kt++) {
        const uint4 cur0 = b0, cur1 = b1;
        if (kt + 1 < KT) {
            const uint4* wp = wbase + (size_t)(kt + 1) * 16 * 32;
            b0 = __ldg(wp);
            b1 = __ldg(wp + 32);
        }
        #pragma unroll
        for (int m = 0; m < 4; m++) {
            unsigned a0, a1, a2, a3;
            ldsm_x4(a0, a1, a2, a3,
                    abase + (unsigned)(m * 16 * SLAB * 2 + kt * 32));
            mma16816(C[m][0], a0, a1, a2, a3, cur0.x, cur0.y);
            mma16816(C[m][1], a0, a1, a2, a3, cur0.z, cur0.w);
            mma16816(C[m][2], a0, a1, a2, a3, cur1.x, cur1.y);
            mma16816(C[m][3], a0, a1, a2, a3, cur1.z, cur1.w);
        }
    }
}

// ---------------- kernel 2: MLP, 64 rows/CTA, occ 2 ----------------
// smem: slab 64x568 halves | dirsm 64f | d3s 512f | d4s 512f | rwsm 768f | parth 1536f
#define SM_DIR   72704
#define SM_D3    72960
#define SM_D4    75008
#define SM_RW    77056
#define SM_PARTH 80128
#define SM_TOTAL 86272

__global__ __launch_bounds__(256, 2) void mlp_mma_kernel(
    const float* __restrict__ vd,
    const float* __restrict__ db1, const float* __restrict__ db2,
    const float* __restrict__ vb0, const float* __restrict__ vb1,
    const float* __restrict__ vw0, const float* __restrict__ vw1,
    const float* __restrict__ rw,  const float* __restrict__ rbias,
    float* __restrict__ out)
{
    extern __shared__ char dyn[];
    __half* slab = (__half*)dyn;
    float* dirsm = (float*)(dyn + SM_DIR);
    float* d3s   = (float*)(dyn + SM_D3);
    float* d4s   = (float*)(dyn + SM_D4);
    float* rwsm  = (float*)(dyn + SM_RW);
    float* parth = (float*)(dyn + SM_PARTH);

    const int t = threadIdx.x;
    const int w = t >> 5, lane = t & 31;
    const int gr = lane >> 2, gc = lane & 3;
    const int rs0 = blockIdx.x * ROWS_CTA;

    // rw -> smem
    for (int i = t; i < 768; i += 256) rwsm[i] = rw[i];

    // dir encoding: 2 rays x 32 cols (cols >= 27 zero)
    if (t < 64) {
        int rayi = t >> 5, c = t & 31;
        int rg = blockIdx.x * 2 + rayi;
        float v = 0.f;
        if (c < 3) v = vd[rg * 3 + c];
        else if (c < 15) { int j = c - 3;  v = sinf(vd[rg * 3 + (j % 3)] * (float)(1 << (j / 3))); }
        else if (c < 27) { int j = c - 15; v = cosf(vd[rg * 3 + (j % 3)] * (float)(1 << (j / 3))); }
        dirsm[t] = v;
        // zero feat pad cols 40..47
        *(uint4*)&slab[t * SLAB + 40] = make_uint4(0, 0, 0, 0);
    }

    // feat (fp16) -> slab cols 0..39
    #pragma unroll
    for (int i = t; i < ROWS_CTA * 20; i += 256) {
        int r = i / 20, c = i % 20;
        *(unsigned*)&slab[r * SLAB + c * 2] =
            *(const unsigned*)&g_feat_h[(rs0 + r) * FEAT_DIM + c * 2];
    }
    __syncthreads();

    // dir contribution folded to per-(ray,channel) scalars (fp32)
    {
        const int ry = t >> 7;
        const int ch = (t & 127) * 2;
        const float* dv = &dirsm[ry * 32];
        float a3 = 0.f, b3 = 0.f, a4 = 0.f, b4 = 0.f;
        #pragma unroll
        for (int j = 0; j < 27; j++) {
            const float d = dv[j];
            const float2 w3 = *(const float2*)&vw0[(256 + j) * 256 + ch];
            const float2 w4 = *(const float2*)&vw1[(512 + j) * 256 + ch];
            a3 += d * w3.x; b3 += d * w3.y;
            a4 += d * w4.x; b4 += d * w4.y;
        }
        *(float2*)&d3s[ry * 256 + ch] = make_float2(a3, b3);
        *(float2*)&d4s[ry * 256 + ch] = make_float2(a4, b4);
    }
    __syncthreads();

    // ---- L1: feat(cols 0..47) @ W1 -> h1 (relu) -> cols 64..127 ----
    {
        const int mp = w & 1, nq = w >> 1;
        float C[2][2][4] = {};
        run_layer2<3, 2, 4>(slab, 0, mp, gr, gc, Wpk, nq, lane, C);
        #pragma unroll
        for (int mm = 0; mm < 2; mm++) {
            const int r0 = mp * 32 + mm * 16 + gr;
            #pragma unroll
            for (int nt = 0; nt < 2; nt++) {
                int n = nq * 16 + nt * 8 + 2 * gc;
                float2 b = *(const float2*)&db1[n];
                __half2 lo = __floats2half2_rn(fmaxf(C[mm][nt][0] + b.x, 0.f), fmaxf(C[mm][nt][1] + b.y, 0.f));
                __half2 hi = __floats2half2_rn(fmaxf(C[mm][nt][2] + b.x, 0.f), fmaxf(C[mm][nt][3] + b.y, 0.f));
                *(__half2*)&slab[r0 * SLAB + 64 + n]       = lo;
                *(__half2*)&slab[(r0 + 8) * SLAB + 64 + n] = hi;
            }
        }
    }
    __syncthreads();

    // ---- L2: h1(cols 64..127) @ W2 -> x (cols 256..511); density ----
    {
        float C[4][4][4] = {};
        run_layer4<4>(slab, 64, lane, Wpk + 1536, w, C);
        #pragma unroll
        for (int m = 0; m < 4; m++) {
            const int r0 = m * 16 + gr;
            if (w == 0 && gc == 0) {
                float xa = C[m][0][0] + __ldg(&db2[0]) - 1.0f;
                float xb = C[m][0][2] + __ldg(&db2[0]) - 1.0f;
                out[RGB_ELEMS + rs0 + r0]     = fmaxf(xa, 0.f) + log1pf(expf(-fabsf(xa)));
                out[RGB_ELEMS + rs0 + r0 + 8] = fmaxf(xb, 0.f) + log1pf(expf(-fabsf(xb)));
            }
            #pragma unroll
            for (int nt = 0; nt < 4; nt++) {
                int n = w * 32 + nt * 8 + 2 * gc;
                float2 b = *(const float2*)&db2[n];
                __half2 lo = __floats2half2_rn(C[m][nt][0] + b.x, C[m][nt][1] + b.y);
                __half2 hi = __floats2half2_rn(C[m][nt][2] + b.x, C[m][nt][3] + b.y);
                *(__half2*)&slab[r0 * SLAB + 256 + n]       = lo;
                *(__half2*)&slab[(r0 + 8) * SLAB + 256 + n] = hi;
            }
        }
    }
    __syncthreads();

    // ---- L3: x(cols 256..511) @ W3 + dirfold -> h2 (relu) -> cols 0..255 ----
    {
        float C[4][4][4] = {};
        run_layer4<16>(slab, 256, lane, Wpk + 9728, w, C);
        #pragma unroll
        for (int m = 0; m < 4; m++) {
            const int r0 = m * 16 + gr;
            const int ry = m >> 1;
            #pragma unroll
            for (int nt = 0; nt < 4; nt++) {
                int n = w * 32 + nt * 8 + 2 * gc;
                float2 b = *(const float2*)&vb0[n];
                float2 d = *(const float2*)&d3s[ry * 256 + n];
                float b0 = b.x + d.x, b1 = b.y + d.y;
                __half2 lo = __floats2half2_rn(fmaxf(C[m][nt][0] + b0, 0.f), fmaxf(C[m][nt][1] + b1, 0.f));
                __half2 hi = __floats2half2_rn(fmaxf(C[m][nt][2] + b0, 0.f), fmaxf(C[m][nt][3] + b1, 0.f));
                *(__half2*)&slab[r0 * SLAB + n]       = lo;
                *(__half2*)&slab[(r0 + 8) * SLAB + n] = hi;
            }
        }
    }
    __syncthreads();

    // ---- L4: [h2|x](cols 0..511) @ W4 + dirfold -> h3 (regs) -> rgb head ----
    {
        float C[4][4][4] = {};
        run_layer4<32>(slab, 0, lane, Wpk + 42496, w, C);

        #pragma unroll
        for (int m = 0; m < 4; m++) {
            const int r0 = m * 16 + gr;
            const int ry = m >> 1;
            float pl[3] = {0.f, 0.f, 0.f}, ph[3] = {0.f, 0.f, 0.f};
            #pragma unroll
            for (int nt = 0; nt < 4; nt++) {
                int n = w * 32 + nt * 8 + 2 * gc;
                float2 b = *(const float2*)&vb1[n];
                float2 d = *(const float2*)&d4s[ry * 256 + n];
                float b0 = b.x + d.x, b1 = b.y + d.y;
                float h0 = fmaxf(C[m][nt][0] + b0, 0.f);
                float h1 = fmaxf(C[m][nt][1] + b1, 0.f);
                float h2 = fmaxf(C[m][nt][2] + b0, 0.f);
                float h3 = fmaxf(C[m][nt][3] + b1, 0.f);
                #pragma unroll
                for (int j = 0; j < 3; j++) {
                    pl[j] += h0 * rwsm[n * 3 + j] + h1 * rwsm[(n + 1) * 3 + j];
                    ph[j] += h2 * rwsm[n * 3 + j] + h3 * rwsm[(n + 1) * 3 + j];
                }
            }
            #pragma unroll
            for (int j = 0; j < 3; j++) {
                pl[j] += __shfl_xor_sync(0xffffffffu, pl[j], 1);
                pl[j] += __shfl_xor_sync(0xffffffffu, pl[j], 2);
                ph[j] += __shfl_xor_sync(0xffffffffu, ph[j], 1);
                ph[j] += __shfl_xor_sync(0xffffffffu, ph[j], 2);
            }
            if (gc == 0) {
                #pragma unroll
                for (int j = 0; j < 3; j++) {
                    parth[r0 * 24 + w * 3 + j]       = pl[j];
                    parth[(r0 + 8) * 24 + w * 3 + j] = ph[j];
                }
            }
        }
    }
    __syncthreads();

    if (t < ROWS_CTA) {
        #pragma unroll
        for (int j = 0; j < 3; j++) {
            float s = __ldg(&rbias[j]);
            #pragma unroll
            for (int q = 0; q < 8; q++) s += parth[t * 24 + q * 3 + j];
            float sig = 1.0f / (1.0f + expf(-s));
            out[(rs0 + t) * 3 + j] = sig * 1.002f - 0.001f;
        }
    }
}

// ---------------- launch ----------------
extern "C" void kernel_launch(void* const* d_in, const int* in_sizes, int n_in,
                              void* d_out, int out_size)
{
    const float* means = (const float*)d_in[0];
    const float* stds  = (const float*)d_in[1];
    const float* vd    = (const float*)d_in[2];
    const float* table = (const float*)d_in[3];
    const float* dw1   = (const float*)d_in[4];
    const float* db1   = (const float*)d_in[5];
    const float* dw2   = (const float*)d_in[6];
    const float* db2   = (const float*)d_in[7];
    const float* vw0   = (const float*)d_in[8];
    const float* vb0   = (const float*)d_in[9];
    const float* vw1   = (const float*)d_in[10];
    const float* vb1   = (const float*)d_in[11];
    const float* rw    = (const float*)d_in[12];
    const float* rb    = (const float*)d_in[13];
    float* out = (float*)d_out;

    cudaFuncSetAttribute(mlp_mma_kernel, cudaFuncAttributeMaxDynamicSharedMemorySize, SM_TOTAL);

    grid_encode_kernel<<<ENC_BLOCKS + PREP_BLOCKS, 128>>>(
        means, stds, (const float4*)table, dw1, dw2, vw0, vw1);

    mlp_mma_kernel<<<NCTA, 256, SM_TOTAL>>>(vd, db1, db2, vb0, vb1,
                                            vw0, vw1, rw, rb, out);
}